// round 4
// baseline (speedup 1.0000x reference)
#include <cuda_runtime.h>
#include <cuda_bf16.h>
#include <cstdint>

#define CAP    65536
#define HID    512
#define NH     8
#define BATCH  2048
#define TOPK   32
#define NCODE  256
#define CHUNK  256
#define NCHUNK (CAP / CHUNK)
#define QCHUNK (BATCH / CHUNK)

// ---------------- scratch (static device globals; no allocation) ----------------
__device__ float         g_W[NH * HID];
__device__ unsigned char g_qcode[BATCH];
__device__ unsigned char g_kcode[CAP];
__device__ int           g_hist[NCHUNK * NCODE];
__device__ int           g_bstart[NCODE];
__device__ int           g_bcnt[NCODE];
__device__ int           g_sorted[CAP];
__device__ int           g_qhist[QCHUNK * NCODE];
__device__ int           g_qbstart[NCODE];
__device__ int           g_qbcnt[NCODE];
__device__ int           g_qsorted[BATCH];
__device__ __nv_bfloat16 g_Ahi[BATCH * HID];
__device__ __nv_bfloat16 g_Alo[BATCH * HID];
__device__ __nv_bfloat16 g_Bhi[HID * HID];
__device__ __nv_bfloat16 g_Blo[HID * HID];

// ---------------- K1: W[n][h] = sum_d hp[n][h][d] ----------------
__global__ void k_reduce_w(const float* __restrict__ hp) {
    int i = blockIdx.x * blockDim.x + threadIdx.x;
    if (i < NH * HID) {
        float s = 0.f;
#pragma unroll
        for (int d = 0; d < 16; d++) s += hp[i * 16 + d];
        g_W[i] = s;
    }
}

// ---------------- K2: LSH code, 4 rows per warp (FFMA-bound, fp32 exact) -------
__global__ void k_hash(const float* __restrict__ X, int rows, unsigned char* __restrict__ out) {
    __shared__ float4 sW4[NH * 128];
    int tid = threadIdx.x;
    for (int i = tid; i < NH * 128; i += 256) sW4[i] = ((const float4*)g_W)[i];
    __syncthreads();
    int warp = tid >> 5, lane = tid & 31;
    int r0 = blockIdx.x * 32 + warp * 4;
    if (r0 >= rows) return;
    float acc[4][NH];
#pragma unroll
    for (int r = 0; r < 4; r++)
#pragma unroll
        for (int n = 0; n < NH; n++) acc[r][n] = 0.f;

#pragma unroll
    for (int i = 0; i < 4; i++) {
        int j = lane + 32 * i;
        float4 xv[4];
#pragma unroll
        for (int r = 0; r < 4; r++)
            xv[r] = ((const float4*)(X + (size_t)(r0 + r) * HID))[j];
#pragma unroll
        for (int n = 0; n < NH; n++) {
            float4 wv = sW4[n * 128 + j];
#pragma unroll
            for (int r = 0; r < 4; r++)
                acc[r][n] += xv[r].x * wv.x + xv[r].y * wv.y + xv[r].z * wv.z + xv[r].w * wv.w;
        }
    }
#pragma unroll
    for (int r = 0; r < 4; r++)
#pragma unroll
        for (int n = 0; n < NH; n++) {
#pragma unroll
            for (int off = 16; off > 0; off >>= 1)
                acc[r][n] += __shfl_xor_sync(0xffffffffu, acc[r][n], off);
        }
    if (lane == 0) {
#pragma unroll
        for (int r = 0; r < 4; r++) {
            unsigned c = 0;
#pragma unroll
            for (int n = 0; n < NH; n++)
                if (acc[r][n] > 0.f) c |= (1u << n);
            out[r0 + r] = (unsigned char)c;
        }
    }
}

// ---------------- K3: counting sort (hist -> parallel scans -> scatter) --------
__global__ void k_hist_g(const unsigned char* __restrict__ codes, int* __restrict__ hist) {
    __shared__ int sh[NCODE];
    int tid = threadIdx.x;
    sh[tid] = 0;
    __syncthreads();
    atomicAdd(&sh[codes[blockIdx.x * CHUNK + tid]], 1);
    __syncthreads();
    hist[blockIdx.x * NCODE + tid] = sh[tid];
}

// one block per code: exclusive scan of chunk counts, total -> bcnt
__global__ void k_scan_code(int* __restrict__ hist, int* __restrict__ bcnt, int nchunk) {
    int code = blockIdx.x, t = threadIdx.x;
    __shared__ int s[256];
    int v = (t < nchunk) ? hist[t * NCODE + code] : 0;
    s[t] = v;
    __syncthreads();
    for (int off = 1; off < 256; off <<= 1) {
        int tmp = (t >= off) ? s[t - off] : 0;
        __syncthreads();
        s[t] += tmp;
        __syncthreads();
    }
    if (t < nchunk) hist[t * NCODE + code] = s[t] - v;  // exclusive within code
    if (t == 255) bcnt[code] = s[255];
}

// 1 block: exclusive scan of bucket totals
__global__ void k_scan_total(const int* __restrict__ bcnt, int* __restrict__ bstart) {
    int t = threadIdx.x;
    __shared__ int s[256];
    int v = bcnt[t];
    s[t] = v;
    __syncthreads();
    for (int off = 1; off < 256; off <<= 1) {
        int tmp = (t >= off) ? s[t - off] : 0;
        __syncthreads();
        s[t] += tmp;
        __syncthreads();
    }
    bstart[t] = s[t] - v;
}

__global__ void k_scatter_g(const unsigned char* __restrict__ codes,
                            const int* __restrict__ hist,
                            const int* __restrict__ bstart,
                            int* __restrict__ sorted) {
    __shared__ unsigned char sc[CHUNK];
    int tid = threadIdx.x;
    int gi = blockIdx.x * CHUNK + tid;
    sc[tid] = codes[gi];
    __syncthreads();
    int my = sc[tid];
    int rank = 0;
    for (int i = 0; i < tid; i++) rank += (sc[i] == my);
    sorted[bstart[my] + hist[blockIdx.x * NCODE + my] + rank] = gi;
}

// ---------------- K4: grouped attention; outputs split-bf16 directly -----------
__global__ void k_attn(const float* __restrict__ query,
                       const float* __restrict__ mkeys,
                       const float* __restrict__ mvals) {
    int code = blockIdx.x;
    int qcnt = g_qbcnt[code];
    if ((int)blockIdx.y * 8 >= qcnt) return;
    int tid = threadIdx.x;

    __shared__ int   sidx[TOPK];
    __shared__ float sq[8][HID];
    __shared__ float ssc[8][TOPK];
    __shared__ float swt[8][TOPK];
    __shared__ int   sqi[8];

    int kcnt = g_bcnt[code];
    if (kcnt >= TOPK) {
        if (tid < TOPK) sidx[tid] = g_sorted[g_bstart[code] + tid];
    } else if (tid < 32) {
        // exact (distance, index)-ordered fallback; astronomically rare
        int lane = tid;
        int got = 0;
        for (int d = 0; d <= NH && got < TOPK; d++) {
            for (int base = 0; base < CAP; base += 32) {
                int c = g_kcode[base + lane];
                bool hit = (__popc(c ^ code) == d);
                unsigned m = __ballot_sync(0xffffffffu, hit);
                int r = __popc(m & ((1u << lane) - 1u));
                if (hit && got + r < TOPK) sidx[got + r] = base + lane;
                got += __popc(m);
                if (got >= TOPK) break;
            }
        }
    }

    int qbase = g_qbstart[code];
    for (int g = blockIdx.y; g * 8 < qcnt; g += 32) {
        int qs = g * 8;
        int nq = qcnt - qs; if (nq > 8) nq = 8;
        if (tid < nq) sqi[tid] = g_qsorted[qbase + qs + tid];
        __syncthreads();
        for (int i = tid; i < nq * HID; i += 256) {
            int q = i >> 9, h = i & (HID - 1);
            sq[q][h] = query[(size_t)sqi[q] * HID + h];
        }
        __syncthreads();

        if (tid < 128) {
            int sub = tid & 7, kg = tid >> 3;
            const float4* kr0 = (const float4*)(mkeys + (size_t)sidx[kg] * HID);
            const float4* kr1 = (const float4*)(mkeys + (size_t)sidx[kg + 16] * HID);
            float a0[8], a1[8];
#pragma unroll
            for (int q = 0; q < 8; q++) { a0[q] = 0.f; a1[q] = 0.f; }
#pragma unroll
            for (int j = 0; j < 16; j++) {
                int jj = sub + 8 * j;
                float4 k0 = kr0[jj];
                float4 k1 = kr1[jj];
#pragma unroll
                for (int q = 0; q < 8; q++) {
                    float4 qv = ((const float4*)sq[q])[jj];
                    a0[q] += k0.x * qv.x + k0.y * qv.y + k0.z * qv.z + k0.w * qv.w;
                    a1[q] += k1.x * qv.x + k1.y * qv.y + k1.z * qv.z + k1.w * qv.w;
                }
            }
#pragma unroll
            for (int q = 0; q < 8; q++) {
#pragma unroll
                for (int off = 1; off < 8; off <<= 1) {
                    a0[q] += __shfl_xor_sync(0xffffffffu, a0[q], off);
                    a1[q] += __shfl_xor_sync(0xffffffffu, a1[q], off);
                }
            }
            if (sub == 0) {
#pragma unroll
                for (int q = 0; q < 8; q++) {
                    ssc[q][kg]      = a0[q] * 0.04419417382415922f;
                    ssc[q][kg + 16] = a1[q] * 0.04419417382415922f;
                }
            }
        }
        __syncthreads();

        {
            int q = tid >> 5, lane = tid & 31;
            float s = ssc[q][lane];
            float mx = s;
#pragma unroll
            for (int off = 16; off > 0; off >>= 1)
                mx = fmaxf(mx, __shfl_xor_sync(0xffffffffu, mx, off));
            float e = expf(s - mx);
            float sum = e;
#pragma unroll
            for (int off = 16; off > 0; off >>= 1)
                sum += __shfl_xor_sync(0xffffffffu, sum, off);
            swt[q][lane] = e / sum;
        }
        __syncthreads();

        float o0[8], o1[8];
#pragma unroll
        for (int q = 0; q < 8; q++) { o0[q] = 0.f; o1[q] = 0.f; }
#pragma unroll 4
        for (int k = 0; k < TOPK; k++) {
            const float* vr = mvals + (size_t)sidx[k] * HID;
            float v0 = vr[tid];
            float v1 = vr[tid + 256];
#pragma unroll
            for (int q = 0; q < 8; q++) {
                float w = swt[q][k];
                o0[q] += w * v0;
                o1[q] += w * v1;
            }
        }
        for (int q = 0; q < nq; q++) {
            size_t base = (size_t)sqi[q] * HID;
            float v = o0[q];
            __nv_bfloat16 h = __float2bfloat16(v);
            g_Ahi[base + tid] = h;
            g_Alo[base + tid] = __float2bfloat16(v - __bfloat162float(h));
            v = o1[q];
            h = __float2bfloat16(v);
            g_Ahi[base + tid + 256] = h;
            g_Alo[base + tid + 256] = __float2bfloat16(v - __bfloat162float(h));
        }
        __syncthreads();
    }
}

// ---------------- K5a: split W into bf16 hi/lo ----------------
__global__ void k_convw(const float* __restrict__ W) {
    int i = blockIdx.x * blockDim.x + threadIdx.x;  // 512*512 elems
    float v = W[i];
    __nv_bfloat16 h = __float2bfloat16(v);
    g_Bhi[i] = h;
    g_Blo[i] = __float2bfloat16(v - __bfloat162float(h));
}

// ---------------- K5b: tensor-core GEMM, 3xBF16 split ----------------
__device__ __forceinline__ void ldm_x4(uint32_t* r, uint32_t addr) {
    asm volatile("ldmatrix.sync.aligned.m8n8.x4.shared.b16 {%0,%1,%2,%3}, [%4];"
                 : "=r"(r[0]), "=r"(r[1]), "=r"(r[2]), "=r"(r[3]) : "r"(addr));
}
__device__ __forceinline__ void mma_bf16(float* d, const uint32_t* a, uint32_t b0, uint32_t b1) {
    asm volatile("mma.sync.aligned.m16n8k16.row.col.f32.bf16.bf16.f32 "
                 "{%0,%1,%2,%3},{%4,%5,%6,%7},{%8,%9},{%0,%1,%2,%3};"
                 : "+f"(d[0]), "+f"(d[1]), "+f"(d[2]), "+f"(d[3])
                 : "r"(a[0]), "r"(a[1]), "r"(a[2]), "r"(a[3]), "r"(b0), "r"(b1));
}

__global__ void k_gemm_tc(const float* __restrict__ bias, float* __restrict__ C) {
    const int LDS = 40;  // bf16 units per row (80B: 8 distinct 16B banks / 8 rows)
    __shared__ __align__(16) __nv_bfloat16 sA[128 * LDS];
    __shared__ __align__(16) __nv_bfloat16 sB[64 * LDS];
    int tid = threadIdx.x;             // 256 threads = 8 warps
    int w = tid >> 5, lane = tid & 31;
    int bm = blockIdx.y * 128, bn = blockIdx.x * 64;
    int wm = (w >> 1) * 32, wn = (w & 1) * 32;

    float acc[2][4][4];
#pragma unroll
    for (int mt = 0; mt < 2; mt++)
#pragma unroll
        for (int n8 = 0; n8 < 4; n8++)
#pragma unroll
            for (int i = 0; i < 4; i++) acc[mt][n8][i] = 0.f;

    uint32_t sA_u = (uint32_t)__cvta_generic_to_shared(sA);
    uint32_t sB_u = (uint32_t)__cvta_generic_to_shared(sB);
    int lrow = lane & 15, lch = lane >> 4;

    const __nv_bfloat16* Asrcs[3];
    const __nv_bfloat16* Bsrcs[3];
    // pass 0: Ahi*Bhi, pass 1: Alo*Bhi, pass 2: Ahi*Blo  (Alo*Blo ~2^-18, dropped)
    Asrcs[0] = g_Ahi; Bsrcs[0] = g_Bhi;
    Asrcs[1] = g_Alo; Bsrcs[1] = g_Bhi;
    Asrcs[2] = g_Ahi; Bsrcs[2] = g_Blo;

    for (int p = 0; p < 3; p++) {
        const __nv_bfloat16* Asrc = Asrcs[p];
        const __nv_bfloat16* Bsrc = Bsrcs[p];
        for (int k0 = 0; k0 < HID; k0 += 32) {
            __syncthreads();
            // A: 128 rows x 32 bf16 -> 512 x 16B; 2 per thread
#pragma unroll
            for (int t = 0; t < 2; t++) {
                int idx = tid + t * 256;
                int row = idx >> 2, ch = idx & 3;
                uint4 v = *(const uint4*)(Asrc + (size_t)(bm + row) * HID + k0 + ch * 8);
                *(uint4*)(sA + row * LDS + ch * 8) = v;
            }
            // B: 64 rows x 32 bf16 -> 256 x 16B; 1 per thread
            {
                int row = tid >> 2, ch = tid & 3;
                uint4 v = *(const uint4*)(Bsrc + (size_t)(bn + row) * HID + k0 + ch * 8);
                *(uint4*)(sB + row * LDS + ch * 8) = v;
            }
            __syncthreads();
#pragma unroll
            for (int ks = 0; ks < 2; ks++) {
                uint32_t a[2][4], b[2][4];
#pragma unroll
                for (int mt = 0; mt < 2; mt++)
                    ldm_x4(a[mt], sA_u + 2 * ((wm + mt * 16 + lrow) * LDS + ks * 16 + lch * 8));
#pragma unroll
                for (int nt = 0; nt < 2; nt++)
                    ldm_x4(b[nt], sB_u + 2 * ((wn + nt * 16 + lrow) * LDS + ks * 16 + lch * 8));
#pragma unroll
                for (int mt = 0; mt < 2; mt++)
#pragma unroll
                    for (int n8 = 0; n8 < 4; n8++) {
                        int nt = n8 >> 1, hh = n8 & 1;
                        mma_bf16(acc[mt][n8], a[mt], b[nt][hh], b[nt][hh + 2]);
                    }
            }
        }
    }

    int r0 = bm + wm + (lane >> 2);
#pragma unroll
    for (int mt = 0; mt < 2; mt++) {
#pragma unroll
        for (int n8 = 0; n8 < 4; n8++) {
            int col = bn + wn + n8 * 8 + (lane & 3) * 2;
            float b0 = bias[col], b1 = bias[col + 1];
            int r = r0 + mt * 16;
            C[(size_t)r * HID + col]           = acc[mt][n8][0] + b0;
            C[(size_t)r * HID + col + 1]       = acc[mt][n8][1] + b1;
            C[(size_t)(r + 8) * HID + col]     = acc[mt][n8][2] + b0;
            C[(size_t)(r + 8) * HID + col + 1] = acc[mt][n8][3] + b1;
        }
    }
}

// ---------------- launch ----------------
extern "C" void kernel_launch(void* const* d_in, const int* in_sizes, int n_in,
                              void* d_out, int out_size) {
    const float* query = (const float*)d_in[0];
    const float* mkeys = (const float*)d_in[1];
    const float* mvals = (const float*)d_in[2];
    const float* hproj = (const float*)d_in[3];
    const float* outw  = (const float*)d_in[4];
    const float* outb  = (const float*)d_in[5];
    float* out = (float*)d_out;

    unsigned char *qcode, *kcode;
    int *hist, *bstart, *bcnt, *sorted, *qhist, *qbstart, *qbcnt, *qsorted;
    cudaGetSymbolAddress((void**)&qcode, g_qcode);
    cudaGetSymbolAddress((void**)&kcode, g_kcode);
    cudaGetSymbolAddress((void**)&hist, g_hist);
    cudaGetSymbolAddress((void**)&bstart, g_bstart);
    cudaGetSymbolAddress((void**)&bcnt, g_bcnt);
    cudaGetSymbolAddress((void**)&sorted, g_sorted);
    cudaGetSymbolAddress((void**)&qhist, g_qhist);
    cudaGetSymbolAddress((void**)&qbstart, g_qbstart);
    cudaGetSymbolAddress((void**)&qbcnt, g_qbcnt);
    cudaGetSymbolAddress((void**)&qsorted, g_qsorted);

    k_reduce_w<<<(NH * HID + 255) / 256, 256>>>(hproj);
    k_convw<<<(HID * HID) / 256, 256>>>(outw);
    k_hash<<<CAP / 32, 256>>>(mkeys, CAP, kcode);
    k_hash<<<BATCH / 32, 256>>>(query, BATCH, qcode);
    k_hist_g<<<NCHUNK, CHUNK>>>(kcode, hist);
    k_scan_code<<<NCODE, 256>>>(hist, bcnt, NCHUNK);
    k_scan_total<<<1, NCODE>>>(bcnt, bstart);
    k_scatter_g<<<NCHUNK, CHUNK>>>(kcode, hist, bstart, sorted);
    k_hist_g<<<QCHUNK, CHUNK>>>(qcode, qhist);
    k_scan_code<<<NCODE, 256>>>(qhist, qbcnt, QCHUNK);
    k_scan_total<<<1, NCODE>>>(qbcnt, qbstart);
    k_scatter_g<<<QCHUNK, CHUNK>>>(qcode, qhist, qbstart, qsorted);
    dim3 agrid(NCODE, 32);
    k_attn<<<agrid, 256>>>(query, mkeys, mvals);
    dim3 ggrid(HID / 64, BATCH / 128);
    k_gemm_tc<<<ggrid, 256>>>(outb, out);
}

// round 5
// speedup vs baseline: 1.4524x; 1.4524x over previous
#include <cuda_runtime.h>
#include <cuda_bf16.h>
#include <cstdint>

#define CAP    65536
#define HID    512
#define NH     8
#define BATCH  2048
#define TOPK   32
#define NCODE  256
#define CHUNK  256
#define NCHUNK (CAP / CHUNK)
#define QCHUNK (BATCH / CHUNK)

// ---------------- scratch (static device globals; no allocation) ----------------
__device__ float         g_W[NH * HID];
__device__ unsigned char g_qcode[BATCH];
__device__ unsigned char g_kcode[CAP];
__device__ int           g_hist[NCHUNK * NCODE];
__device__ int           g_bstart[NCODE];
__device__ int           g_bcnt[NCODE];
__device__ int           g_sorted[CAP];
__device__ int           g_qhist[QCHUNK * NCODE];
__device__ int           g_qbstart[NCODE];
__device__ int           g_qbcnt[NCODE];
__device__ int           g_qsorted[BATCH];
__device__ float         g_memout[BATCH * HID];

// ---------------- K1: W[n][h] = sum_d hp[n][h][d] ----------------
__global__ void k_reduce_w(const float* __restrict__ hp) {
    int i = blockIdx.x * blockDim.x + threadIdx.x;
    if (i < NH * HID) {
        float s = 0.f;
#pragma unroll
        for (int d = 0; d < 16; d++) s += hp[i * 16 + d];
        g_W[i] = s;
    }
}

// ---------------- K2: LSH code, R rows per warp (fp32 exact) ----------------
template <int R>
__global__ void k_hash(const float* __restrict__ X, unsigned char* __restrict__ out) {
    __shared__ float4 sW4[NH * 128];
    int tid = threadIdx.x;
    for (int i = tid; i < NH * 128; i += 256) sW4[i] = ((const float4*)g_W)[i];
    __syncthreads();
    int warp = tid >> 5, lane = tid & 31;
    int r0 = (blockIdx.x * 8 + warp) * R;
    float acc[R][NH];
#pragma unroll
    for (int r = 0; r < R; r++)
#pragma unroll
        for (int n = 0; n < NH; n++) acc[r][n] = 0.f;

#pragma unroll
    for (int i = 0; i < 4; i++) {
        int j = lane + 32 * i;
        float4 xv[R];
#pragma unroll
        for (int r = 0; r < R; r++)
            xv[r] = ((const float4*)(X + (size_t)(r0 + r) * HID))[j];
#pragma unroll
        for (int n = 0; n < NH; n++) {
            float4 wv = sW4[n * 128 + j];
#pragma unroll
            for (int r = 0; r < R; r++)
                acc[r][n] += xv[r].x * wv.x + xv[r].y * wv.y + xv[r].z * wv.z + xv[r].w * wv.w;
        }
    }
#pragma unroll
    for (int r = 0; r < R; r++)
#pragma unroll
        for (int n = 0; n < NH; n++) {
#pragma unroll
            for (int off = 16; off > 0; off >>= 1)
                acc[r][n] += __shfl_xor_sync(0xffffffffu, acc[r][n], off);
        }
    if (lane == 0) {
#pragma unroll
        for (int r = 0; r < R; r++) {
            unsigned c = 0;
#pragma unroll
            for (int n = 0; n < NH; n++)
                if (acc[r][n] > 0.f) c |= (1u << n);
            out[r0 + r] = (unsigned char)c;
        }
    }
}

// ---------------- K3: counting sort (hist -> parallel scans -> scatter) --------
__global__ void k_hist_g(const unsigned char* __restrict__ codes, int* __restrict__ hist) {
    __shared__ int sh[NCODE];
    int tid = threadIdx.x;
    sh[tid] = 0;
    __syncthreads();
    atomicAdd(&sh[codes[blockIdx.x * CHUNK + tid]], 1);
    __syncthreads();
    hist[blockIdx.x * NCODE + tid] = sh[tid];
}

__global__ void k_scan_code(int* __restrict__ hist, int* __restrict__ bcnt, int nchunk) {
    int code = blockIdx.x, t = threadIdx.x;
    __shared__ int s[256];
    int v = (t < nchunk) ? hist[t * NCODE + code] : 0;
    s[t] = v;
    __syncthreads();
    for (int off = 1; off < 256; off <<= 1) {
        int tmp = (t >= off) ? s[t - off] : 0;
        __syncthreads();
        s[t] += tmp;
        __syncthreads();
    }
    if (t < nchunk) hist[t * NCODE + code] = s[t] - v;
    if (t == 255) bcnt[code] = s[255];
}

__global__ void k_scan_total(const int* __restrict__ bcnt, int* __restrict__ bstart) {
    int t = threadIdx.x;
    __shared__ int s[256];
    int v = bcnt[t];
    s[t] = v;
    __syncthreads();
    for (int off = 1; off < 256; off <<= 1) {
        int tmp = (t >= off) ? s[t - off] : 0;
        __syncthreads();
        s[t] += tmp;
        __syncthreads();
    }
    bstart[t] = s[t] - v;
}

__global__ void k_scatter_g(const unsigned char* __restrict__ codes,
                            const int* __restrict__ hist,
                            const int* __restrict__ bstart,
                            int* __restrict__ sorted) {
    __shared__ unsigned char sc[CHUNK];
    int tid = threadIdx.x;
    int gi = blockIdx.x * CHUNK + tid;
    sc[tid] = codes[gi];
    __syncthreads();
    int my = sc[tid];
    int rank = 0;
    for (int i = 0; i < tid; i++) rank += (sc[i] == my);
    sorted[bstart[my] + hist[blockIdx.x * NCODE + my] + rank] = gi;
}

// ---------------- K4: grouped attention (fp32 memout, R2-identical) ------------
__global__ void k_attn(const float* __restrict__ query,
                       const float* __restrict__ mkeys,
                       const float* __restrict__ mvals) {
    int code = blockIdx.x;
    int qcnt = g_qbcnt[code];
    if ((int)blockIdx.y * 8 >= qcnt) return;
    int tid = threadIdx.x;

    __shared__ int   sidx[TOPK];
    __shared__ float sq[8][HID];
    __shared__ float ssc[8][TOPK];
    __shared__ float swt[8][TOPK];
    __shared__ int   sqi[8];

    int kcnt = g_bcnt[code];
    if (kcnt >= TOPK) {
        if (tid < TOPK) sidx[tid] = g_sorted[g_bstart[code] + tid];
    } else if (tid < 32) {
        int lane = tid;
        int got = 0;
        for (int d = 0; d <= NH && got < TOPK; d++) {
            for (int base = 0; base < CAP; base += 32) {
                int c = g_kcode[base + lane];
                bool hit = (__popc(c ^ code) == d);
                unsigned m = __ballot_sync(0xffffffffu, hit);
                int r = __popc(m & ((1u << lane) - 1u));
                if (hit && got + r < TOPK) sidx[got + r] = base + lane;
                got += __popc(m);
                if (got >= TOPK) break;
            }
        }
    }

    int qbase = g_qbstart[code];
    for (int g = blockIdx.y; g * 8 < qcnt; g += 32) {
        int qs = g * 8;
        int nq = qcnt - qs; if (nq > 8) nq = 8;
        if (tid < nq) sqi[tid] = g_qsorted[qbase + qs + tid];
        __syncthreads();
        for (int i = tid; i < nq * HID; i += 256) {
            int q = i >> 9, h = i & (HID - 1);
            sq[q][h] = query[(size_t)sqi[q] * HID + h];
        }
        __syncthreads();

        if (tid < 128) {
            int sub = tid & 7, kg = tid >> 3;
            const float4* kr0 = (const float4*)(mkeys + (size_t)sidx[kg] * HID);
            const float4* kr1 = (const float4*)(mkeys + (size_t)sidx[kg + 16] * HID);
            float a0[8], a1[8];
#pragma unroll
            for (int q = 0; q < 8; q++) { a0[q] = 0.f; a1[q] = 0.f; }
#pragma unroll
            for (int j = 0; j < 16; j++) {
                int jj = sub + 8 * j;
                float4 k0 = kr0[jj];
                float4 k1 = kr1[jj];
#pragma unroll
                for (int q = 0; q < 8; q++) {
                    float4 qv = ((const float4*)sq[q])[jj];
                    a0[q] += k0.x * qv.x + k0.y * qv.y + k0.z * qv.z + k0.w * qv.w;
                    a1[q] += k1.x * qv.x + k1.y * qv.y + k1.z * qv.z + k1.w * qv.w;
                }
            }
#pragma unroll
            for (int q = 0; q < 8; q++) {
#pragma unroll
                for (int off = 1; off < 8; off <<= 1) {
                    a0[q] += __shfl_xor_sync(0xffffffffu, a0[q], off);
                    a1[q] += __shfl_xor_sync(0xffffffffu, a1[q], off);
                }
            }
            if (sub == 0) {
#pragma unroll
                for (int q = 0; q < 8; q++) {
                    ssc[q][kg]      = a0[q] * 0.04419417382415922f;
                    ssc[q][kg + 16] = a1[q] * 0.04419417382415922f;
                }
            }
        }
        __syncthreads();

        {
            int q = tid >> 5, lane = tid & 31;
            float s = ssc[q][lane];
            float mx = s;
#pragma unroll
            for (int off = 16; off > 0; off >>= 1)
                mx = fmaxf(mx, __shfl_xor_sync(0xffffffffu, mx, off));
            float e = expf(s - mx);
            float sum = e;
#pragma unroll
            for (int off = 16; off > 0; off >>= 1)
                sum += __shfl_xor_sync(0xffffffffu, sum, off);
            swt[q][lane] = e / sum;
        }
        __syncthreads();

        float o0[8], o1[8];
#pragma unroll
        for (int q = 0; q < 8; q++) { o0[q] = 0.f; o1[q] = 0.f; }
#pragma unroll 4
        for (int k = 0; k < TOPK; k++) {
            const float* vr = mvals + (size_t)sidx[k] * HID;
            float v0 = vr[tid];
            float v1 = vr[tid + 256];
#pragma unroll
            for (int q = 0; q < 8; q++) {
                float w = swt[q][k];
                o0[q] += w * v0;
                o1[q] += w * v1;
            }
        }
        for (int q = 0; q < nq; q++) {
            g_memout[(size_t)sqi[q] * HID + tid]       = o0[q];
            g_memout[(size_t)sqi[q] * HID + tid + 256] = o1[q];
        }
        __syncthreads();
    }
}

// ---------------- K5: fused single-pass 3xBF16 tensor-core GEMM ----------------
__device__ __forceinline__ void ldm_x4(uint32_t* r, uint32_t addr) {
    asm volatile("ldmatrix.sync.aligned.m8n8.x4.shared.b16 {%0,%1,%2,%3}, [%4];"
                 : "=r"(r[0]), "=r"(r[1]), "=r"(r[2]), "=r"(r[3]) : "r"(addr));
}
__device__ __forceinline__ void mma_bf16(float* d, const uint32_t* a, uint32_t b0, uint32_t b1) {
    asm volatile("mma.sync.aligned.m16n8k16.row.col.f32.bf16.bf16.f32 "
                 "{%0,%1,%2,%3},{%4,%5,%6,%7},{%8,%9},{%0,%1,%2,%3};"
                 : "+f"(d[0]), "+f"(d[1]), "+f"(d[2]), "+f"(d[3])
                 : "r"(a[0]), "r"(a[1]), "r"(a[2]), "r"(a[3]), "r"(b0), "r"(b1));
}
__device__ __forceinline__ void split2(float x, float y, uint32_t& hi, uint32_t& lo) {
    __nv_bfloat162 h = __float22bfloat162_rn(make_float2(x, y));
    float2 hf = __bfloat1622float2(h);
    __nv_bfloat162 l = __float22bfloat162_rn(make_float2(x - hf.x, y - hf.y));
    hi = *(uint32_t*)&h;
    lo = *(uint32_t*)&l;
}

__global__ void k_gemm_tc(const float* __restrict__ Wt,
                          const float* __restrict__ bias,
                          float* __restrict__ C) {
    const int LDS = 40;  // bf16 per smem row (80B -> 8 distinct 16B banks)
    __shared__ __align__(16) __nv_bfloat16 sAhi[128 * LDS];
    __shared__ __align__(16) __nv_bfloat16 sAlo[128 * LDS];
    __shared__ __align__(16) __nv_bfloat16 sBhi[64 * LDS];
    __shared__ __align__(16) __nv_bfloat16 sBlo[64 * LDS];
    int tid = threadIdx.x;             // 256 threads = 8 warps
    int w = tid >> 5, lane = tid & 31;
    int bm = blockIdx.y * 128, bn = blockIdx.x * 64;
    int wm = (w >> 1) * 32, wn = (w & 1) * 32;

    float acc[2][4][4];
#pragma unroll
    for (int mt = 0; mt < 2; mt++)
#pragma unroll
        for (int n8 = 0; n8 < 4; n8++)
#pragma unroll
            for (int i = 0; i < 4; i++) acc[mt][n8][i] = 0.f;

    uint32_t sAhi_u = (uint32_t)__cvta_generic_to_shared(sAhi);
    uint32_t sAlo_u = (uint32_t)__cvta_generic_to_shared(sAlo);
    uint32_t sBhi_u = (uint32_t)__cvta_generic_to_shared(sBhi);
    uint32_t sBlo_u = (uint32_t)__cvta_generic_to_shared(sBlo);
    int lrow = lane & 15, lch = lane >> 4;

    for (int k0 = 0; k0 < HID; k0 += 32) {
        __syncthreads();
        // A: 128 rows x 32 fp32 = 1024 float4; 4 per thread -> hi/lo bf16 smem
#pragma unroll
        for (int t = 0; t < 4; t++) {
            int f = tid + t * 256;
            int row = f >> 3, c4 = f & 7;
            float4 v = *(const float4*)&g_memout[(size_t)(bm + row) * HID + k0 + c4 * 4];
            uint32_t h0, l0, h1, l1;
            split2(v.x, v.y, h0, l0);
            split2(v.z, v.w, h1, l1);
            *(uint2*)(sAhi + row * LDS + c4 * 4) = make_uint2(h0, h1);
            *(uint2*)(sAlo + row * LDS + c4 * 4) = make_uint2(l0, l1);
        }
        // B: 64 rows x 32 fp32 = 512 float4; 2 per thread
#pragma unroll
        for (int t = 0; t < 2; t++) {
            int f = tid + t * 256;
            int row = f >> 3, c4 = f & 7;
            float4 v = *(const float4*)&Wt[(size_t)(bn + row) * HID + k0 + c4 * 4];
            uint32_t h0, l0, h1, l1;
            split2(v.x, v.y, h0, l0);
            split2(v.z, v.w, h1, l1);
            *(uint2*)(sBhi + row * LDS + c4 * 4) = make_uint2(h0, h1);
            *(uint2*)(sBlo + row * LDS + c4 * 4) = make_uint2(l0, l1);
        }
        __syncthreads();
#pragma unroll
        for (int ks = 0; ks < 2; ks++) {
            uint32_t ahi[2][4], alo[2][4], bhi[2][4], blo[2][4];
            int aoff = 2 * ((wm + lrow) * LDS + ks * 16 + lch * 8);
            int boff = 2 * ((wn + lrow) * LDS + ks * 16 + lch * 8);
#pragma unroll
            for (int mt = 0; mt < 2; mt++) {
                ldm_x4(ahi[mt], sAhi_u + aoff + 2 * mt * 16 * LDS);
                ldm_x4(alo[mt], sAlo_u + aoff + 2 * mt * 16 * LDS);
            }
#pragma unroll
            for (int nt = 0; nt < 2; nt++) {
                ldm_x4(bhi[nt], sBhi_u + boff + 2 * nt * 16 * LDS);
                ldm_x4(blo[nt], sBlo_u + boff + 2 * nt * 16 * LDS);
            }
#pragma unroll
            for (int mt = 0; mt < 2; mt++)
#pragma unroll
                for (int n8 = 0; n8 < 4; n8++) {
                    int nt = n8 >> 1, hh = n8 & 1;
                    mma_bf16(acc[mt][n8], ahi[mt], bhi[nt][hh], bhi[nt][hh + 2]);
                    mma_bf16(acc[mt][n8], alo[mt], bhi[nt][hh], bhi[nt][hh + 2]);
                    mma_bf16(acc[mt][n8], ahi[mt], blo[nt][hh], blo[nt][hh + 2]);
                }
        }
    }

    int r0 = bm + wm + (lane >> 2);
#pragma unroll
    for (int mt = 0; mt < 2; mt++) {
#pragma unroll
        for (int n8 = 0; n8 < 4; n8++) {
            int col = bn + wn + n8 * 8 + (lane & 3) * 2;
            float b0 = bias[col], b1 = bias[col + 1];
            int r = r0 + mt * 16;
            C[(size_t)r * HID + col]           = acc[mt][n8][0] + b0;
            C[(size_t)r * HID + col + 1]       = acc[mt][n8][1] + b1;
            C[(size_t)(r + 8) * HID + col]     = acc[mt][n8][2] + b0;
            C[(size_t)(r + 8) * HID + col + 1] = acc[mt][n8][3] + b1;
        }
    }
}

// ---------------- launch ----------------
extern "C" void kernel_launch(void* const* d_in, const int* in_sizes, int n_in,
                              void* d_out, int out_size) {
    const float* query = (const float*)d_in[0];
    const float* mkeys = (const float*)d_in[1];
    const float* mvals = (const float*)d_in[2];
    const float* hproj = (const float*)d_in[3];
    const float* outw  = (const float*)d_in[4];
    const float* outb  = (const float*)d_in[5];
    float* out = (float*)d_out;

    unsigned char *qcode, *kcode;
    int *hist, *bstart, *bcnt, *sorted, *qhist, *qbstart, *qbcnt, *qsorted;
    cudaGetSymbolAddress((void**)&qcode, g_qcode);
    cudaGetSymbolAddress((void**)&kcode, g_kcode);
    cudaGetSymbolAddress((void**)&hist, g_hist);
    cudaGetSymbolAddress((void**)&bstart, g_bstart);
    cudaGetSymbolAddress((void**)&bcnt, g_bcnt);
    cudaGetSymbolAddress((void**)&sorted, g_sorted);
    cudaGetSymbolAddress((void**)&qhist, g_qhist);
    cudaGetSymbolAddress((void**)&qbstart, g_qbstart);
    cudaGetSymbolAddress((void**)&qbcnt, g_qbcnt);
    cudaGetSymbolAddress((void**)&qsorted, g_qsorted);

    k_reduce_w<<<(NH * HID + 255) / 256, 256>>>(hproj);
    k_hash<4><<<CAP / 32, 256>>>(mkeys, kcode);
    k_hash<1><<<BATCH / 8, 256>>>(query, qcode);
    k_hist_g<<<NCHUNK, CHUNK>>>(kcode, hist);
    k_scan_code<<<NCODE, 256>>>(hist, bcnt, NCHUNK);
    k_scan_total<<<1, NCODE>>>(bcnt, bstart);
    k_scatter_g<<<NCHUNK, CHUNK>>>(kcode, hist, bstart, sorted);
    k_hist_g<<<QCHUNK, CHUNK>>>(qcode, qhist);
    k_scan_code<<<NCODE, 256>>>(qhist, qbcnt, QCHUNK);
    k_scan_total<<<1, NCODE>>>(qbcnt, qbstart);
    k_scatter_g<<<QCHUNK, CHUNK>>>(qcode, qhist, qbstart, qsorted);
    dim3 agrid(NCODE, 32);
    k_attn<<<agrid, 256>>>(query, mkeys, mvals);
    dim3 ggrid(HID / 64, BATCH / 128);
    k_gemm_tc<<<ggrid, 256>>>(outw, outb, out);
}

// round 6
// speedup vs baseline: 1.5421x; 1.0617x over previous
#include <cuda_runtime.h>
#include <cuda_bf16.h>
#include <cstdint>

#define CAP    65536
#define HID    512
#define NH     8
#define BATCH  2048
#define TOPK   32
#define NCODE  256
#define CHUNK  256
#define NCHUNK (CAP / CHUNK)
#define QCHUNK (BATCH / CHUNK)

// ---------------- scratch (static device globals; no allocation) ----------------
__device__ float         g_W[NH * HID];
__device__ unsigned char g_qcode[BATCH];
__device__ unsigned char g_kcode[CAP];
__device__ int           g_hist[NCHUNK * NCODE];
__device__ int           g_bstart[NCODE];
__device__ int           g_bcnt[NCODE];
__device__ int           g_sorted[CAP];
__device__ int           g_qhist[QCHUNK * NCODE];
__device__ int           g_qbstart[NCODE];
__device__ int           g_qbcnt[NCODE];
__device__ int           g_qsorted[BATCH];
__device__ float         g_memout[BATCH * HID];
__device__ unsigned      g_arrive;   // grid-barrier arrival counter

// ---------------- K1: W[n][h] = sum_d hp[n][h][d]; also reset grid barrier -----
__global__ void k_reduce_w(const float* __restrict__ hp) {
    int i = blockIdx.x * blockDim.x + threadIdx.x;
    if (i == 0) g_arrive = 0u;
    if (i < NH * HID) {
        float s = 0.f;
#pragma unroll
        for (int d = 0; d < 16; d++) s += hp[i * 16 + d];
        g_W[i] = s;
    }
}

// ---------------- K2: LSH code, R rows per warp (fp32 exact) ----------------
template <int R>
__global__ void k_hash(const float* __restrict__ X, unsigned char* __restrict__ out) {
    __shared__ float4 sW4[NH * 128];
    int tid = threadIdx.x;
    for (int i = tid; i < NH * 128; i += 256) sW4[i] = ((const float4*)g_W)[i];
    __syncthreads();
    int warp = tid >> 5, lane = tid & 31;
    int r0 = (blockIdx.x * 8 + warp) * R;
    float acc[R][NH];
#pragma unroll
    for (int r = 0; r < R; r++)
#pragma unroll
        for (int n = 0; n < NH; n++) acc[r][n] = 0.f;

#pragma unroll
    for (int i = 0; i < 4; i++) {
        int j = lane + 32 * i;
        float4 xv[R];
#pragma unroll
        for (int r = 0; r < R; r++)
            xv[r] = ((const float4*)(X + (size_t)(r0 + r) * HID))[j];
#pragma unroll
        for (int n = 0; n < NH; n++) {
            float4 wv = sW4[n * 128 + j];
#pragma unroll
            for (int r = 0; r < R; r++)
                acc[r][n] += xv[r].x * wv.x + xv[r].y * wv.y + xv[r].z * wv.z + xv[r].w * wv.w;
        }
    }
#pragma unroll
    for (int r = 0; r < R; r++)
#pragma unroll
        for (int n = 0; n < NH; n++) {
#pragma unroll
            for (int off = 16; off > 0; off >>= 1)
                acc[r][n] += __shfl_xor_sync(0xffffffffu, acc[r][n], off);
        }
    if (lane == 0) {
#pragma unroll
        for (int r = 0; r < R; r++) {
            unsigned c = 0;
#pragma unroll
            for (int n = 0; n < NH; n++)
                if (acc[r][n] > 0.f) c |= (1u << n);
            out[r0 + r] = (unsigned char)c;
        }
    }
}

// ---------------- K3: fully fused dual counting sort (1 kernel, grid barriers) --
__device__ __forceinline__ void gbar(unsigned target) {
    __syncthreads();
    if (threadIdx.x == 0) {
        __threadfence();
        atomicAdd(&g_arrive, 1u);
        while (atomicAdd(&g_arrive, 0u) < target) __nanosleep(64);
    }
    __syncthreads();
}

__global__ void __launch_bounds__(256) k_sort_fused(void) {
    int tid = threadIdx.x, b = blockIdx.x;
    __shared__ int s[NCODE];
    __shared__ unsigned char sc[CHUNK];
    __shared__ int sq8[QCHUNK];

    // ---- P1: per-chunk histograms (keys: all blocks; queries: blocks 0..7) ----
    s[tid] = 0;
    __syncthreads();
    atomicAdd(&s[g_kcode[b * CHUNK + tid]], 1);
    __syncthreads();
    g_hist[b * NCODE + tid] = s[tid];
    if (b < QCHUNK) {
        __syncthreads();
        s[tid] = 0;
        __syncthreads();
        atomicAdd(&s[g_qcode[b * CHUNK + tid]], 1);
        __syncthreads();
        g_qhist[b * NCODE + tid] = s[tid];
    }
    gbar(256);

    // ---- P2: block b == code b: scan chunk counts -> per-chunk bases + totals --
    {
        int v = g_hist[tid * NCODE + b];   // tid = chunk
        s[tid] = v;
        __syncthreads();
        for (int off = 1; off < 256; off <<= 1) {
            int tmp = (tid >= off) ? s[tid - off] : 0;
            __syncthreads();
            s[tid] += tmp;
            __syncthreads();
        }
        g_hist[tid * NCODE + b] = s[tid] - v;
        if (tid == 255) g_bcnt[b] = s[255];
    }
    {
        if (tid < QCHUNK) sq8[tid] = g_qhist[tid * NCODE + b];
        __syncthreads();
        if (tid == 0) {
            int run = 0;
#pragma unroll
            for (int c = 0; c < QCHUNK; c++) { int v = sq8[c]; sq8[c] = run; run += v; }
            g_qbcnt[b] = run;
        }
        __syncthreads();
        if (tid < QCHUNK) g_qhist[tid * NCODE + b] = sq8[tid];
    }
    gbar(512);

    // ---- P3: scan bucket totals (block 0 keys, block 1 queries) ----
    if (b == 0) {
        int v = g_bcnt[tid];
        s[tid] = v;
        __syncthreads();
        for (int off = 1; off < 256; off <<= 1) {
            int tmp = (tid >= off) ? s[tid - off] : 0;
            __syncthreads();
            s[tid] += tmp;
            __syncthreads();
        }
        g_bstart[tid] = s[tid] - v;
    } else if (b == 1) {
        int v = g_qbcnt[tid];
        s[tid] = v;
        __syncthreads();
        for (int off = 1; off < 256; off <<= 1) {
            int tmp = (tid >= off) ? s[tid - off] : 0;
            __syncthreads();
            s[tid] += tmp;
            __syncthreads();
        }
        g_qbstart[tid] = s[tid] - v;
    }
    gbar(768);

    // ---- P4: stable scatter (keys: all blocks; queries: blocks 0..7) ----
    {
        int gi = b * CHUNK + tid;
        sc[tid] = g_kcode[gi];
        __syncthreads();
        int my = sc[tid];
        int rank = 0;
        for (int i = 0; i < tid; i++) rank += (sc[i] == my);
        g_sorted[g_bstart[my] + g_hist[b * NCODE + my] + rank] = gi;
    }
    if (b < QCHUNK) {
        int gi = b * CHUNK + tid;
        __syncthreads();
        sc[tid] = g_qcode[gi];
        __syncthreads();
        int my = sc[tid];
        int rank = 0;
        for (int i = 0; i < tid; i++) rank += (sc[i] == my);
        g_qsorted[g_qbstart[my] + g_qhist[b * NCODE + my] + rank] = gi;
    }
}

// ---------------- K4: grouped attention (unchanged from R5) --------------------
__global__ void k_attn(const float* __restrict__ query,
                       const float* __restrict__ mkeys,
                       const float* __restrict__ mvals) {
    int code = blockIdx.x;
    int qcnt = g_qbcnt[code];
    if ((int)blockIdx.y * 8 >= qcnt) return;
    int tid = threadIdx.x;

    __shared__ int   sidx[TOPK];
    __shared__ float sq[8][HID];
    __shared__ float ssc[8][TOPK];
    __shared__ float swt[8][TOPK];
    __shared__ int   sqi[8];

    int kcnt = g_bcnt[code];
    if (kcnt >= TOPK) {
        if (tid < TOPK) sidx[tid] = g_sorted[g_bstart[code] + tid];
    } else if (tid < 32) {
        int lane = tid;
        int got = 0;
        for (int d = 0; d <= NH && got < TOPK; d++) {
            for (int base = 0; base < CAP; base += 32) {
                int c = g_kcode[base + lane];
                bool hit = (__popc(c ^ code) == d);
                unsigned m = __ballot_sync(0xffffffffu, hit);
                int r = __popc(m & ((1u << lane) - 1u));
                if (hit && got + r < TOPK) sidx[got + r] = base + lane;
                got += __popc(m);
                if (got >= TOPK) break;
            }
        }
    }

    int qbase = g_qbstart[code];
    for (int g = blockIdx.y; g * 8 < qcnt; g += 32) {
        int qs = g * 8;
        int nq = qcnt - qs; if (nq > 8) nq = 8;
        if (tid < nq) sqi[tid] = g_qsorted[qbase + qs + tid];
        __syncthreads();
        for (int i = tid; i < nq * HID; i += 256) {
            int q = i >> 9, h = i & (HID - 1);
            sq[q][h] = query[(size_t)sqi[q] * HID + h];
        }
        __syncthreads();

        if (tid < 128) {
            int sub = tid & 7, kg = tid >> 3;
            const float4* kr0 = (const float4*)(mkeys + (size_t)sidx[kg] * HID);
            const float4* kr1 = (const float4*)(mkeys + (size_t)sidx[kg + 16] * HID);
            float a0[8], a1[8];
#pragma unroll
            for (int q = 0; q < 8; q++) { a0[q] = 0.f; a1[q] = 0.f; }
#pragma unroll
            for (int j = 0; j < 16; j++) {
                int jj = sub + 8 * j;
                float4 k0 = kr0[jj];
                float4 k1 = kr1[jj];
#pragma unroll
                for (int q = 0; q < 8; q++) {
                    float4 qv = ((const float4*)sq[q])[jj];
                    a0[q] += k0.x * qv.x + k0.y * qv.y + k0.z * qv.z + k0.w * qv.w;
                    a1[q] += k1.x * qv.x + k1.y * qv.y + k1.z * qv.z + k1.w * qv.w;
                }
            }
#pragma unroll
            for (int q = 0; q < 8; q++) {
#pragma unroll
                for (int off = 1; off < 8; off <<= 1) {
                    a0[q] += __shfl_xor_sync(0xffffffffu, a0[q], off);
                    a1[q] += __shfl_xor_sync(0xffffffffu, a1[q], off);
                }
            }
            if (sub == 0) {
#pragma unroll
                for (int q = 0; q < 8; q++) {
                    ssc[q][kg]      = a0[q] * 0.04419417382415922f;
                    ssc[q][kg + 16] = a1[q] * 0.04419417382415922f;
                }
            }
        }
        __syncthreads();

        {
            int q = tid >> 5, lane = tid & 31;
            float s = ssc[q][lane];
            float mx = s;
#pragma unroll
            for (int off = 16; off > 0; off >>= 1)
                mx = fmaxf(mx, __shfl_xor_sync(0xffffffffu, mx, off));
            float e = expf(s - mx);
            float sum = e;
#pragma unroll
            for (int off = 16; off > 0; off >>= 1)
                sum += __shfl_xor_sync(0xffffffffu, sum, off);
            swt[q][lane] = e / sum;
        }
        __syncthreads();

        float o0[8], o1[8];
#pragma unroll
        for (int q = 0; q < 8; q++) { o0[q] = 0.f; o1[q] = 0.f; }
#pragma unroll 4
        for (int k = 0; k < TOPK; k++) {
            const float* vr = mvals + (size_t)sidx[k] * HID;
            float v0 = vr[tid];
            float v1 = vr[tid + 256];
#pragma unroll
            for (int q = 0; q < 8; q++) {
                float w = swt[q][k];
                o0[q] += w * v0;
                o1[q] += w * v1;
            }
        }
        for (int q = 0; q < nq; q++) {
            g_memout[(size_t)sqi[q] * HID + tid]       = o0[q];
            g_memout[(size_t)sqi[q] * HID + tid + 256] = o1[q];
        }
        __syncthreads();
    }
}

// ---------------- K5: fused single-pass 3xBF16 tensor-core GEMM (unchanged) ----
__device__ __forceinline__ void ldm_x4(uint32_t* r, uint32_t addr) {
    asm volatile("ldmatrix.sync.aligned.m8n8.x4.shared.b16 {%0,%1,%2,%3}, [%4];"
                 : "=r"(r[0]), "=r"(r[1]), "=r"(r[2]), "=r"(r[3]) : "r"(addr));
}
__device__ __forceinline__ void mma_bf16(float* d, const uint32_t* a, uint32_t b0, uint32_t b1) {
    asm volatile("mma.sync.aligned.m16n8k16.row.col.f32.bf16.bf16.f32 "
                 "{%0,%1,%2,%3},{%4,%5,%6,%7},{%8,%9},{%0,%1,%2,%3};"
                 : "+f"(d[0]), "+f"(d[1]), "+f"(d[2]), "+f"(d[3])
                 : "r"(a[0]), "r"(a[1]), "r"(a[2]), "r"(a[3]), "r"(b0), "r"(b1));
}
__device__ __forceinline__ void split2(float x, float y, uint32_t& hi, uint32_t& lo) {
    __nv_bfloat162 h = __float22bfloat162_rn(make_float2(x, y));
    float2 hf = __bfloat1622float2(h);
    __nv_bfloat162 l = __float22bfloat162_rn(make_float2(x - hf.x, y - hf.y));
    hi = *(uint32_t*)&h;
    lo = *(uint32_t*)&l;
}

__global__ void k_gemm_tc(const float* __restrict__ Wt,
                          const float* __restrict__ bias,
                          float* __restrict__ C) {
    const int LDS = 40;
    __shared__ __align__(16) __nv_bfloat16 sAhi[128 * LDS];
    __shared__ __align__(16) __nv_bfloat16 sAlo[128 * LDS];
    __shared__ __align__(16) __nv_bfloat16 sBhi[64 * LDS];
    __shared__ __align__(16) __nv_bfloat16 sBlo[64 * LDS];
    int tid = threadIdx.x;
    int w = tid >> 5, lane = tid & 31;
    int bm = blockIdx.y * 128, bn = blockIdx.x * 64;
    int wm = (w >> 1) * 32, wn = (w & 1) * 32;

    float acc[2][4][4];
#pragma unroll
    for (int mt = 0; mt < 2; mt++)
#pragma unroll
        for (int n8 = 0; n8 < 4; n8++)
#pragma unroll
            for (int i = 0; i < 4; i++) acc[mt][n8][i] = 0.f;

    uint32_t sAhi_u = (uint32_t)__cvta_generic_to_shared(sAhi);
    uint32_t sAlo_u = (uint32_t)__cvta_generic_to_shared(sAlo);
    uint32_t sBhi_u = (uint32_t)__cvta_generic_to_shared(sBhi);
    uint32_t sBlo_u = (uint32_t)__cvta_generic_to_shared(sBlo);
    int lrow = lane & 15, lch = lane >> 4;

    for (int k0 = 0; k0 < HID; k0 += 32) {
        __syncthreads();
#pragma unroll
        for (int t = 0; t < 4; t++) {
            int f = tid + t * 256;
            int row = f >> 3, c4 = f & 7;
            float4 v = *(const float4*)&g_memout[(size_t)(bm + row) * HID + k0 + c4 * 4];
            uint32_t h0, l0, h1, l1;
            split2(v.x, v.y, h0, l0);
            split2(v.z, v.w, h1, l1);
            *(uint2*)(sAhi + row * LDS + c4 * 4) = make_uint2(h0, h1);
            *(uint2*)(sAlo + row * LDS + c4 * 4) = make_uint2(l0, l1);
        }
#pragma unroll
        for (int t = 0; t < 2; t++) {
            int f = tid + t * 256;
            int row = f >> 3, c4 = f & 7;
            float4 v = *(const float4*)&Wt[(size_t)(bn + row) * HID + k0 + c4 * 4];
            uint32_t h0, l0, h1, l1;
            split2(v.x, v.y, h0, l0);
            split2(v.z, v.w, h1, l1);
            *(uint2*)(sBhi + row * LDS + c4 * 4) = make_uint2(h0, h1);
            *(uint2*)(sBlo + row * LDS + c4 * 4) = make_uint2(l0, l1);
        }
        __syncthreads();
#pragma unroll
        for (int ks = 0; ks < 2; ks++) {
            uint32_t ahi[2][4], alo[2][4], bhi[2][4], blo[2][4];
            int aoff = 2 * ((wm + lrow) * LDS + ks * 16 + lch * 8);
            int boff = 2 * ((wn + lrow) * LDS + ks * 16 + lch * 8);
#pragma unroll
            for (int mt = 0; mt < 2; mt++) {
                ldm_x4(ahi[mt], sAhi_u + aoff + 2 * mt * 16 * LDS);
                ldm_x4(alo[mt], sAlo_u + aoff + 2 * mt * 16 * LDS);
            }
#pragma unroll
            for (int nt = 0; nt < 2; nt++) {
                ldm_x4(bhi[nt], sBhi_u + boff + 2 * nt * 16 * LDS);
                ldm_x4(blo[nt], sBlo_u + boff + 2 * nt * 16 * LDS);
            }
#pragma unroll
            for (int mt = 0; mt < 2; mt++)
#pragma unroll
                for (int n8 = 0; n8 < 4; n8++) {
                    int nt = n8 >> 1, hh = n8 & 1;
                    mma_bf16(acc[mt][n8], ahi[mt], bhi[nt][hh], bhi[nt][hh + 2]);
                    mma_bf16(acc[mt][n8], alo[mt], bhi[nt][hh], bhi[nt][hh + 2]);
                    mma_bf16(acc[mt][n8], ahi[mt], blo[nt][hh], blo[nt][hh + 2]);
                }
        }
    }

    int r0 = bm + wm + (lane >> 2);
#pragma unroll
    for (int mt = 0; mt < 2; mt++) {
#pragma unroll
        for (int n8 = 0; n8 < 4; n8++) {
            int col = bn + wn + n8 * 8 + (lane & 3) * 2;
            float b0 = bias[col], b1 = bias[col + 1];
            int r = r0 + mt * 16;
            C[(size_t)r * HID + col]           = acc[mt][n8][0] + b0;
            C[(size_t)r * HID + col + 1]       = acc[mt][n8][1] + b1;
            C[(size_t)(r + 8) * HID + col]     = acc[mt][n8][2] + b0;
            C[(size_t)(r + 8) * HID + col + 1] = acc[mt][n8][3] + b1;
        }
    }
}

// ---------------- launch ----------------
extern "C" void kernel_launch(void* const* d_in, const int* in_sizes, int n_in,
                              void* d_out, int out_size) {
    const float* query = (const float*)d_in[0];
    const float* mkeys = (const float*)d_in[1];
    const float* mvals = (const float*)d_in[2];
    const float* hproj = (const float*)d_in[3];
    const float* outw  = (const float*)d_in[4];
    const float* outb  = (const float*)d_in[5];
    float* out = (float*)d_out;

    unsigned char *qcode, *kcode;
    cudaGetSymbolAddress((void**)&qcode, g_qcode);
    cudaGetSymbolAddress((void**)&kcode, g_kcode);

    k_reduce_w<<<(NH * HID + 255) / 256, 256>>>(hproj);
    k_hash<4><<<CAP / 32, 256>>>(mkeys, kcode);
    k_hash<1><<<BATCH / 8, 256>>>(query, qcode);
    k_sort_fused<<<NCHUNK, CHUNK>>>();
    dim3 agrid(NCODE, 32);
    k_attn<<<agrid, 256>>>(query, mkeys, mvals);
    dim3 ggrid(HID / 64, BATCH / 128);
    k_gemm_tc<<<ggrid, 256>>>(outw, outb, out);
}

// round 7
// speedup vs baseline: 1.5882x; 1.0299x over previous
#include <cuda_runtime.h>
#include <cuda_bf16.h>
#include <cstdint>

#define CAP    65536
#define HID    512
#define NH     8
#define BATCH  2048
#define TOPK   32
#define NCODE  256
#define CHUNK  256
#define NCHUNK (CAP / CHUNK)
#define QCHUNK (BATCH / CHUNK)

// ---------------- scratch (static device globals; no allocation) ----------------
__device__ float         g_W[NH * HID];
__device__ unsigned char g_qcode[BATCH];
__device__ unsigned char g_kcode[CAP];
__device__ int           g_hist[NCHUNK * NCODE];
__device__ int           g_bstart[NCODE];
__device__ int           g_bcnt[NCODE];
__device__ int           g_sorted[CAP];
__device__ int           g_qhist[QCHUNK * NCODE];
__device__ int           g_qbstart[NCODE];
__device__ int           g_qbcnt[NCODE];
__device__ int           g_qsorted[BATCH];
__device__ float         g_memout[BATCH * HID];
__device__ unsigned      g_arrive;   // grid-barrier arrival counter

// ---------------- K1: W[n][h] = sum_d hp[n][h][d]; also reset grid barrier -----
__global__ void k_reduce_w(const float* __restrict__ hp) {
    int i = blockIdx.x * blockDim.x + threadIdx.x;
    if (i == 0) g_arrive = 0u;
    if (i < NH * HID) {
        float s = 0.f;
#pragma unroll
        for (int d = 0; d < 16; d++) s += hp[i * 16 + d];
        g_W[i] = s;
    }
}

// ---------------- K2: LSH code, R rows per warp (fp32 exact) ----------------
template <int R>
__global__ void k_hash(const float* __restrict__ X, unsigned char* __restrict__ out) {
    __shared__ float4 sW4[NH * 128];
    int tid = threadIdx.x;
    for (int i = tid; i < NH * 128; i += 256) sW4[i] = ((const float4*)g_W)[i];
    __syncthreads();
    int warp = tid >> 5, lane = tid & 31;
    int r0 = (blockIdx.x * 8 + warp) * R;
    float acc[R][NH];
#pragma unroll
    for (int r = 0; r < R; r++)
#pragma unroll
        for (int n = 0; n < NH; n++) acc[r][n] = 0.f;

#pragma unroll
    for (int i = 0; i < 4; i++) {
        int j = lane + 32 * i;
        float4 xv[R];
#pragma unroll
        for (int r = 0; r < R; r++)
            xv[r] = ((const float4*)(X + (size_t)(r0 + r) * HID))[j];
#pragma unroll
        for (int n = 0; n < NH; n++) {
            float4 wv = sW4[n * 128 + j];
#pragma unroll
            for (int r = 0; r < R; r++)
                acc[r][n] += xv[r].x * wv.x + xv[r].y * wv.y + xv[r].z * wv.z + xv[r].w * wv.w;
        }
    }
#pragma unroll
    for (int r = 0; r < R; r++)
#pragma unroll
        for (int n = 0; n < NH; n++) {
#pragma unroll
            for (int off = 16; off > 0; off >>= 1)
                acc[r][n] += __shfl_xor_sync(0xffffffffu, acc[r][n], off);
        }
    if (lane == 0) {
#pragma unroll
        for (int r = 0; r < R; r++) {
            unsigned c = 0;
#pragma unroll
            for (int n = 0; n < NH; n++)
                if (acc[r][n] > 0.f) c |= (1u << n);
            out[r0 + r] = (unsigned char)c;
        }
    }
}

// ---------------- K3: fused dual counting sort (2 grid barriers, ballot ranks) --
__device__ __forceinline__ void gbar(unsigned target) {
    __syncthreads();
    if (threadIdx.x == 0) {
        __threadfence();
        atomicAdd(&g_arrive, 1u);
        while (*(volatile unsigned*)&g_arrive < target) __nanosleep(32);
    }
    __syncthreads();
}

__global__ void __launch_bounds__(256) k_sort_fused(void) {
    int tid = threadIdx.x, b = blockIdx.x;
    int w = tid >> 5, lane = tid & 31;
    __shared__ int whist[8 * NCODE];   // per-warp code counts / later bstart arrays
    __shared__ int s[NCODE];
    __shared__ int sq8[QCHUNK];

    // ---- P1: ballot-stable ranks + per-chunk histograms (keys; queries b<8) ----
    int myk = g_kcode[b * CHUNK + tid];
    for (int i = tid; i < 8 * NCODE; i += 256) whist[i] = 0;
    __syncthreads();
    unsigned km = __match_any_sync(0xffffffffu, myk);
    int klr = __popc(km & ((1u << lane) - 1u));
    if (klr == 0) whist[w * NCODE + myk] = __popc(km);
    __syncthreads();
    int krank = klr;
#pragma unroll
    for (int ww = 0; ww < 8; ww++)
        if (ww < w) krank += whist[ww * NCODE + myk];
    {
        int tot = 0;
#pragma unroll
        for (int ww = 0; ww < 8; ww++) tot += whist[ww * NCODE + tid];
        g_hist[b * NCODE + tid] = tot;
    }
    int myq = 0, qrank = 0;
    if (b < QCHUNK) {
        __syncthreads();
        for (int i = tid; i < 8 * NCODE; i += 256) whist[i] = 0;
        __syncthreads();
        myq = g_qcode[b * CHUNK + tid];
        unsigned qm = __match_any_sync(0xffffffffu, myq);
        int qlr = __popc(qm & ((1u << lane) - 1u));
        if (qlr == 0) whist[w * NCODE + myq] = __popc(qm);
        __syncthreads();
        qrank = qlr;
#pragma unroll
        for (int ww = 0; ww < 8; ww++)
            if (ww < w) qrank += whist[ww * NCODE + myq];
        int qtot = 0;
#pragma unroll
        for (int ww = 0; ww < 8; ww++) qtot += whist[ww * NCODE + tid];
        g_qhist[b * NCODE + tid] = qtot;
    }
    gbar(256);

    // ---- P2: block b == code b: scan chunk counts -> per-chunk bases + totals --
    {
        int v = g_hist[tid * NCODE + b];   // tid = chunk
        s[tid] = v;
        __syncthreads();
        for (int off = 1; off < 256; off <<= 1) {
            int tmp = (tid >= off) ? s[tid - off] : 0;
            __syncthreads();
            s[tid] += tmp;
            __syncthreads();
        }
        g_hist[tid * NCODE + b] = s[tid] - v;
        if (tid == 255) g_bcnt[b] = s[255];
    }
    {
        if (tid < QCHUNK) sq8[tid] = g_qhist[tid * NCODE + b];
        __syncthreads();
        if (tid == 0) {
            int run = 0;
#pragma unroll
            for (int c = 0; c < QCHUNK; c++) { int v = sq8[c]; sq8[c] = run; run += v; }
            g_qbcnt[b] = run;
        }
        __syncthreads();
        if (tid < QCHUNK) g_qhist[tid * NCODE + b] = sq8[tid];
    }
    gbar(512);

    // ---- P3+P4: local bucket-total scans (redundant per block) + scatter -------
    {
        int vb = g_bcnt[tid];
        s[tid] = vb;
        __syncthreads();
        for (int off = 1; off < 256; off <<= 1) {
            int tmp = (tid >= off) ? s[tid - off] : 0;
            __syncthreads();
            s[tid] += tmp;
            __syncthreads();
        }
        whist[tid] = s[tid] - vb;          // bstart (local)
        int vq = g_qbcnt[tid];
        s[tid] = vq;
        __syncthreads();
        for (int off = 1; off < 256; off <<= 1) {
            int tmp = (tid >= off) ? s[tid - off] : 0;
            __syncthreads();
            s[tid] += tmp;
            __syncthreads();
        }
        whist[NCODE + tid] = s[tid] - vq;  // qbstart (local)
        if (b == 0) {
            g_bstart[tid]  = whist[tid];
            g_qbstart[tid] = whist[NCODE + tid];
        }
        __syncthreads();
        g_sorted[whist[myk] + g_hist[b * NCODE + myk] + krank] = b * CHUNK + tid;
        if (b < QCHUNK)
            g_qsorted[whist[NCODE + myq] + g_qhist[b * NCODE + myq] + qrank] = b * CHUNK + tid;
    }
}

// ---------------- K4: grouped attention (y-grid trimmed to 4) ------------------
__global__ void k_attn(const float* __restrict__ query,
                       const float* __restrict__ mkeys,
                       const float* __restrict__ mvals) {
    int code = blockIdx.x;
    int qcnt = g_qbcnt[code];
    if ((int)blockIdx.y * 8 >= qcnt) return;
    int tid = threadIdx.x;

    __shared__ int   sidx[TOPK];
    __shared__ float sq[8][HID];
    __shared__ float ssc[8][TOPK];
    __shared__ float swt[8][TOPK];
    __shared__ int   sqi[8];

    int kcnt = g_bcnt[code];
    if (kcnt >= TOPK) {
        if (tid < TOPK) sidx[tid] = g_sorted[g_bstart[code] + tid];
    } else if (tid < 32) {
        int lane = tid;
        int got = 0;
        for (int d = 0; d <= NH && got < TOPK; d++) {
            for (int base = 0; base < CAP; base += 32) {
                int c = g_kcode[base + lane];
                bool hit = (__popc(c ^ code) == d);
                unsigned m = __ballot_sync(0xffffffffu, hit);
                int r = __popc(m & ((1u << lane) - 1u));
                if (hit && got + r < TOPK) sidx[got + r] = base + lane;
                got += __popc(m);
                if (got >= TOPK) break;
            }
        }
    }

    int qbase = g_qbstart[code];
    for (int g = blockIdx.y; g * 8 < qcnt; g += 4) {
        int qs = g * 8;
        int nq = qcnt - qs; if (nq > 8) nq = 8;
        if (tid < nq) sqi[tid] = g_qsorted[qbase + qs + tid];
        __syncthreads();
        for (int i = tid; i < nq * HID; i += 256) {
            int q = i >> 9, h = i & (HID - 1);
            sq[q][h] = query[(size_t)sqi[q] * HID + h];
        }
        __syncthreads();

        if (tid < 128) {
            int sub = tid & 7, kg = tid >> 3;
            const float4* kr0 = (const float4*)(mkeys + (size_t)sidx[kg] * HID);
            const float4* kr1 = (const float4*)(mkeys + (size_t)sidx[kg + 16] * HID);
            float a0[8], a1[8];
#pragma unroll
            for (int q = 0; q < 8; q++) { a0[q] = 0.f; a1[q] = 0.f; }
#pragma unroll
            for (int j = 0; j < 16; j++) {
                int jj = sub + 8 * j;
                float4 k0 = kr0[jj];
                float4 k1 = kr1[jj];
#pragma unroll
                for (int q = 0; q < 8; q++) {
                    float4 qv = ((const float4*)sq[q])[jj];
                    a0[q] += k0.x * qv.x + k0.y * qv.y + k0.z * qv.z + k0.w * qv.w;
                    a1[q] += k1.x * qv.x + k1.y * qv.y + k1.z * qv.z + k1.w * qv.w;
                }
            }
#pragma unroll
            for (int q = 0; q < 8; q++) {
#pragma unroll
                for (int off = 1; off < 8; off <<= 1) {
                    a0[q] += __shfl_xor_sync(0xffffffffu, a0[q], off);
                    a1[q] += __shfl_xor_sync(0xffffffffu, a1[q], off);
                }
            }
            if (sub == 0) {
#pragma unroll
                for (int q = 0; q < 8; q++) {
                    ssc[q][kg]      = a0[q] * 0.04419417382415922f;
                    ssc[q][kg + 16] = a1[q] * 0.04419417382415922f;
                }
            }
        }
        __syncthreads();

        {
            int q = tid >> 5, lane = tid & 31;
            float s = ssc[q][lane];
            float mx = s;
#pragma unroll
            for (int off = 16; off > 0; off >>= 1)
                mx = fmaxf(mx, __shfl_xor_sync(0xffffffffu, mx, off));
            float e = expf(s - mx);
            float sum = e;
#pragma unroll
            for (int off = 16; off > 0; off >>= 1)
                sum += __shfl_xor_sync(0xffffffffu, sum, off);
            swt[q][lane] = e / sum;
        }
        __syncthreads();

        float o0[8], o1[8];
#pragma unroll
        for (int q = 0; q < 8; q++) { o0[q] = 0.f; o1[q] = 0.f; }
#pragma unroll 4
        for (int k = 0; k < TOPK; k++) {
            const float* vr = mvals + (size_t)sidx[k] * HID;
            float v0 = vr[tid];
            float v1 = vr[tid + 256];
#pragma unroll
            for (int q = 0; q < 8; q++) {
                float w = swt[q][k];
                o0[q] += w * v0;
                o1[q] += w * v1;
            }
        }
        for (int q = 0; q < nq; q++) {
            g_memout[(size_t)sqi[q] * HID + tid]       = o0[q];
            g_memout[(size_t)sqi[q] * HID + tid + 256] = o1[q];
        }
        __syncthreads();
    }
}

// ---------------- K5: fused single-pass 3xBF16 tensor-core GEMM (unchanged) ----
__device__ __forceinline__ void ldm_x4(uint32_t* r, uint32_t addr) {
    asm volatile("ldmatrix.sync.aligned.m8n8.x4.shared.b16 {%0,%1,%2,%3}, [%4];"
                 : "=r"(r[0]), "=r"(r[1]), "=r"(r[2]), "=r"(r[3]) : "r"(addr));
}
__device__ __forceinline__ void mma_bf16(float* d, const uint32_t* a, uint32_t b0, uint32_t b1) {
    asm volatile("mma.sync.aligned.m16n8k16.row.col.f32.bf16.bf16.f32 "
                 "{%0,%1,%2,%3},{%4,%5,%6,%7},{%8,%9},{%0,%1,%2,%3};"
                 : "+f"(d[0]), "+f"(d[1]), "+f"(d[2]), "+f"(d[3])
                 : "r"(a[0]), "r"(a[1]), "r"(a[2]), "r"(a[3]), "r"(b0), "r"(b1));
}
__device__ __forceinline__ void split2(float x, float y, uint32_t& hi, uint32_t& lo) {
    __nv_bfloat162 h = __float22bfloat162_rn(make_float2(x, y));
    float2 hf = __bfloat1622float2(h);
    __nv_bfloat162 l = __float22bfloat162_rn(make_float2(x - hf.x, y - hf.y));
    hi = *(uint32_t*)&h;
    lo = *(uint32_t*)&l;
}

__global__ void k_gemm_tc(const float* __restrict__ Wt,
                          const float* __restrict__ bias,
                          float* __restrict__ C) {
    const int LDS = 40;
    __shared__ __align__(16) __nv_bfloat16 sAhi[128 * LDS];
    __shared__ __align__(16) __nv_bfloat16 sAlo[128 * LDS];
    __shared__ __align__(16) __nv_bfloat16 sBhi[64 * LDS];
    __shared__ __align__(16) __nv_bfloat16 sBlo[64 * LDS];
    int tid = threadIdx.x;
    int w = tid >> 5, lane = tid & 31;
    int bm = blockIdx.y * 128, bn = blockIdx.x * 64;
    int wm = (w >> 1) * 32, wn = (w & 1) * 32;

    float acc[2][4][4];
#pragma unroll
    for (int mt = 0; mt < 2; mt++)
#pragma unroll
        for (int n8 = 0; n8 < 4; n8++)
#pragma unroll
            for (int i = 0; i < 4; i++) acc[mt][n8][i] = 0.f;

    uint32_t sAhi_u = (uint32_t)__cvta_generic_to_shared(sAhi);
    uint32_t sAlo_u = (uint32_t)__cvta_generic_to_shared(sAlo);
    uint32_t sBhi_u = (uint32_t)__cvta_generic_to_shared(sBhi);
    uint32_t sBlo_u = (uint32_t)__cvta_generic_to_shared(sBlo);
    int lrow = lane & 15, lch = lane >> 4;

    for (int k0 = 0; k0 < HID; k0 += 32) {
        __syncthreads();
#pragma unroll
        for (int t = 0; t < 4; t++) {
            int f = tid + t * 256;
            int row = f >> 3, c4 = f & 7;
            float4 v = *(const float4*)&g_memout[(size_t)(bm + row) * HID + k0 + c4 * 4];
            uint32_t h0, l0, h1, l1;
            split2(v.x, v.y, h0, l0);
            split2(v.z, v.w, h1, l1);
            *(uint2*)(sAhi + row * LDS + c4 * 4) = make_uint2(h0, h1);
            *(uint2*)(sAlo + row * LDS + c4 * 4) = make_uint2(l0, l1);
        }
#pragma unroll
        for (int t = 0; t < 2; t++) {
            int f = tid + t * 256;
            int row = f >> 3, c4 = f & 7;
            float4 v = *(const float4*)&Wt[(size_t)(bn + row) * HID + k0 + c4 * 4];
            uint32_t h0, l0, h1, l1;
            split2(v.x, v.y, h0, l0);
            split2(v.z, v.w, h1, l1);
            *(uint2*)(sBhi + row * LDS + c4 * 4) = make_uint2(h0, h1);
            *(uint2*)(sBlo + row * LDS + c4 * 4) = make_uint2(l0, l1);
        }
        __syncthreads();
#pragma unroll
        for (int ks = 0; ks < 2; ks++) {
            uint32_t ahi[2][4], alo[2][4], bhi[2][4], blo[2][4];
            int aoff = 2 * ((wm + lrow) * LDS + ks * 16 + lch * 8);
            int boff = 2 * ((wn + lrow) * LDS + ks * 16 + lch * 8);
#pragma unroll
            for (int mt = 0; mt < 2; mt++) {
                ldm_x4(ahi[mt], sAhi_u + aoff + 2 * mt * 16 * LDS);
                ldm_x4(alo[mt], sAlo_u + aoff + 2 * mt * 16 * LDS);
            }
#pragma unroll
            for (int nt = 0; nt < 2; nt++) {
                ldm_x4(bhi[nt], sBhi_u + boff + 2 * nt * 16 * LDS);
                ldm_x4(blo[nt], sBlo_u + boff + 2 * nt * 16 * LDS);
            }
#pragma unroll
            for (int mt = 0; mt < 2; mt++)
#pragma unroll
                for (int n8 = 0; n8 < 4; n8++) {
                    int nt = n8 >> 1, hh = n8 & 1;
                    mma_bf16(acc[mt][n8], ahi[mt], bhi[nt][hh], bhi[nt][hh + 2]);
                    mma_bf16(acc[mt][n8], alo[mt], bhi[nt][hh], bhi[nt][hh + 2]);
                    mma_bf16(acc[mt][n8], ahi[mt], blo[nt][hh], blo[nt][hh + 2]);
                }
        }
    }

    int r0 = bm + wm + (lane >> 2);
#pragma unroll
    for (int mt = 0; mt < 2; mt++) {
#pragma unroll
        for (int n8 = 0; n8 < 4; n8++) {
            int col = bn + wn + n8 * 8 + (lane & 3) * 2;
            float b0 = bias[col], b1 = bias[col + 1];
            int r = r0 + mt * 16;
            C[(size_t)r * HID + col]           = acc[mt][n8][0] + b0;
            C[(size_t)r * HID + col + 1]       = acc[mt][n8][1] + b1;
            C[(size_t)(r + 8) * HID + col]     = acc[mt][n8][2] + b0;
            C[(size_t)(r + 8) * HID + col + 1] = acc[mt][n8][3] + b1;
        }
    }
}

// ---------------- launch ----------------
extern "C" void kernel_launch(void* const* d_in, const int* in_sizes, int n_in,
                              void* d_out, int out_size) {
    const float* query = (const float*)d_in[0];
    const float* mkeys = (const float*)d_in[1];
    const float* mvals = (const float*)d_in[2];
    const float* hproj = (const float*)d_in[3];
    const float* outw  = (const float*)d_in[4];
    const float* outb  = (const float*)d_in[5];
    float* out = (float*)d_out;

    unsigned char *qcode, *kcode;
    cudaGetSymbolAddress((void**)&qcode, g_qcode);
    cudaGetSymbolAddress((void**)&kcode, g_kcode);

    k_reduce_w<<<(NH * HID + 255) / 256, 256>>>(hproj);
    k_hash<4><<<CAP / 32, 256>>>(mkeys, kcode);
    k_hash<1><<<BATCH / 8, 256>>>(query, qcode);
    k_sort_fused<<<NCHUNK, CHUNK>>>();
    dim3 agrid(NCODE, 4);
    k_attn<<<agrid, 256>>>(query, mkeys, mvals);
    dim3 ggrid(HID / 64, BATCH / 128);
    k_gemm_tc<<<ggrid, 256>>>(outw, outb, out);
}